// round 6
// baseline (speedup 1.0000x reference)
#include <cuda_runtime.h>

#define NN 100000
#define EE 1600000
#define DIM 128
#define NG 512
#define NLAYER 3
#define AGG_BLOCKS 1024
#define NWARPS (AGG_BLOCKS * 8)
#define BN_EPS 1e-5f

// ---------------- scratch (static device memory; no allocations) ----------------
__device__ float g_h[NN * DIM];        // current features
__device__ float g_hl[NN * DIM];       // GEMM output
__device__ float g_t[NN * DIM];        // pre-BN (post relu) values
__device__ float g_dinv[NN];
__device__ int   g_cnt[NN];
__device__ int   g_off[NN + 1];
__device__ int   g_cur[NN];
__device__ int   g_srcv[EE];           // sorted-by-dst source node ids
__device__ float g_wv[EE];             // sorted edge weights, later fused norm coeffs
__device__ float g_psum[NWARPS * DIM];
__device__ float g_psq[NWARPS * DIM];
__device__ float g_scale[DIM];
__device__ float g_shift[DIM];
__device__ int   g_gstart[NG + 1];

// ---------------- packed fp32x2 helpers (sm_100+ PTX) ----------------
typedef unsigned long long ull;
__device__ __forceinline__ ull pk2(float lo, float hi) {
    ull r; asm("mov.b64 %0, {%1,%2};" : "=l"(r) : "f"(lo), "f"(hi)); return r;
}
__device__ __forceinline__ void upk2(ull v, float& lo, float& hi) {
    asm("mov.b64 {%0,%1}, %2;" : "=f"(lo), "=f"(hi) : "l"(v));
}
__device__ __forceinline__ void fma2(ull& d, ull a, ull b) {
    asm("fma.rn.f32x2 %0, %1, %2, %0;" : "+l"(d) : "l"(a), "l"(b));
}

// ---------------- preprocessing kernels ----------------
__global__ void k_zero_cnt() {
    int i = blockIdx.x * blockDim.x + threadIdx.x;
    if (i < NN) g_cnt[i] = 0;
}

// edge_index is int32 on device (JAX default x64-disabled downcasts int64->int32)
__global__ void k_hist(const int* __restrict__ ei) {
    int e = blockIdx.x * blockDim.x + threadIdx.x;
    if (e < EE) {
        int c = ei[EE + e];  // col = destination
        atomicAdd(&g_cnt[c], 1);
    }
}

// single-block exclusive scan of g_cnt -> g_off, g_cur (1024 threads)
__global__ void k_scan() {
    __shared__ int warpsum[32];
    int tid = threadIdx.x;
    const int CH = (NN + 1023) / 1024;  // 98
    int start = tid * CH;
    int end = min(start + CH, NN);
    int s = 0;
    for (int i = start; i < end; i++) s += g_cnt[i];
    int lane = tid & 31, wid = tid >> 5;
    int incl = s;
    #pragma unroll
    for (int o = 1; o < 32; o <<= 1) {
        int v = __shfl_up_sync(0xFFFFFFFFu, incl, o);
        if (lane >= o) incl += v;
    }
    if (lane == 31) warpsum[wid] = incl;
    __syncthreads();
    if (wid == 0) {
        int v = warpsum[lane];
        #pragma unroll
        for (int o = 1; o < 32; o <<= 1) {
            int u = __shfl_up_sync(0xFFFFFFFFu, v, o);
            if (lane >= o) v += u;
        }
        warpsum[lane] = v;
    }
    __syncthreads();
    int base = (incl - s) + (wid > 0 ? warpsum[wid - 1] : 0);
    int run = base;
    for (int i = start; i < end; i++) {
        int cv = g_cnt[i];
        g_off[i] = run;
        g_cur[i] = run;
        run += cv;
    }
    if (tid == 1023) g_off[NN] = base;  // tail chunk always empty (1023*98 > NN)
}

__global__ void k_sort(const int* __restrict__ ei, const float* __restrict__ ew) {
    int e = blockIdx.x * blockDim.x + threadIdx.x;
    if (e < EE) {
        int d = ei[EE + e];
        int p = atomicAdd(&g_cur[d], 1);
        g_srcv[p] = ei[e];
        g_wv[p] = ew[e];
    }
}

__global__ void k_dinv() {
    int i = blockIdx.x * blockDim.x + threadIdx.x;
    if (i >= NN) return;
    float s = 1.0f;  // self-loop weight
    int p1 = g_off[i + 1];
    for (int p = g_off[i]; p < p1; p++) s += g_wv[p];
    g_dinv[i] = rsqrtf(s);
}

__global__ void k_coef() {
    int i = blockIdx.x * blockDim.x + threadIdx.x;
    if (i >= NN) return;
    float di = g_dinv[i];
    int p1 = g_off[i + 1];
    for (int p = g_off[i]; p < p1; p++)
        g_wv[p] = g_dinv[g_srcv[p]] * g_wv[p] * di;
}

// batch is int32 (same JAX downcast); sorted ascending
__global__ void k_gstart(const int* __restrict__ batch) {
    int i = blockIdx.x * blockDim.x + threadIdx.x;
    if (i >= NN) return;
    int b = batch[i];
    int pb = (i == 0) ? -1 : batch[i - 1];
    for (int g = pb + 1; g <= b; g++) g_gstart[g] = i;
    if (i == NN - 1)
        for (int g = b + 1; g <= NG; g++) g_gstart[g] = NN;
}

// ---------------- GEMM: C[i][o] = sum_k A[i][k] * Wg[o*128+k] ----------------
// 128-row block, 256 threads, both tiles k-major in smem (stride 129 -> conflict free),
// 8 rows x 8 cols per thread, packed fp32x2 FMA.
__global__ void __launch_bounds__(256, 1)
k_gemm(const float* __restrict__ A, const float* __restrict__ Wg,
       float* __restrict__ C, int nrows) {
    extern __shared__ float sm[];
    float* As = sm;             // As[k*129 + r]
    float* Ws = sm + 128 * 129; // Ws[k*129 + o]
    int tid = threadIdx.x;
    int row0 = blockIdx.x * 128;

    for (int idx = tid; idx < 16384; idx += 256) {
        int o = idx >> 7, k = idx & 127;
        Ws[k * 129 + o] = Wg[idx];  // coalesced read; conflict-free write
    }
    for (int idx = tid; idx < 16384; idx += 256) {
        int r = idx >> 7, k = idx & 127;
        int gr = row0 + r;
        As[k * 129 + r] = (gr < nrows) ? A[(size_t)gr * 128 + k] : 0.0f;
    }
    __syncthreads();

    int cg = tid & 15;   // col group: cols cg + 16*j
    int rg = tid >> 4;   // row group: rows rg + 16*m
    ull acc[4][8];
    #pragma unroll
    for (int mp = 0; mp < 4; mp++)
        #pragma unroll
        for (int j = 0; j < 8; j++) acc[mp][j] = 0ull;

    #pragma unroll 2
    for (int k = 0; k < 128; k++) {
        const float* ak = As + k * 129;
        const float* bk = Ws + k * 129;
        float a0 = ak[rg], a1 = ak[rg + 16], a2 = ak[rg + 32], a3 = ak[rg + 48];
        float a4 = ak[rg + 64], a5 = ak[rg + 80], a6 = ak[rg + 96], a7 = ak[rg + 112];
        ull ap0 = pk2(a0, a1), ap1 = pk2(a2, a3), ap2 = pk2(a4, a5), ap3 = pk2(a6, a7);
        #pragma unroll
        for (int j = 0; j < 8; j++) {
            float bj = bk[cg + 16 * j];
            ull bb = pk2(bj, bj);
            fma2(acc[0][j], ap0, bb);
            fma2(acc[1][j], ap1, bb);
            fma2(acc[2][j], ap2, bb);
            fma2(acc[3][j], ap3, bb);
        }
    }

    #pragma unroll
    for (int mp = 0; mp < 4; mp++) {
        int rlo = row0 + rg + 32 * mp;
        int rhi = rlo + 16;
        #pragma unroll
        for (int j = 0; j < 8; j++) {
            float lo, hi;
            upk2(acc[mp][j], lo, hi);
            int col = cg + 16 * j;
            if (rlo < nrows) C[(size_t)rlo * 128 + col] = lo;
            if (rhi < nrows) C[(size_t)rhi * 128 + col] = hi;
        }
    }
}

// ---------------- aggregation: warp per node, CSR gather + bias + relu + BN partials --
__global__ void __launch_bounds__(256)
k_agg(const float* __restrict__ bias) {
    int lane = threadIdx.x & 31;
    int gw = (blockIdx.x * blockDim.x + threadIdx.x) >> 5;
    const float4* hl4 = (const float4*)g_hl;
    float4 bb = *((const float4*)bias + lane);
    float4 ps = make_float4(0, 0, 0, 0);
    float4 pq = make_float4(0, 0, 0, 0);

    for (int i = gw; i < NN; i += NWARPS) {
        float di = g_dinv[i];
        float sn = di * di;
        float4 v = hl4[i * 32 + lane];
        float4 acc;
        acc.x = sn * v.x; acc.y = sn * v.y; acc.z = sn * v.z; acc.w = sn * v.w;
        int p = g_off[i], p1 = g_off[i + 1];
        int s = 0; float w = 0.0f;
        if (p < p1) { s = g_srcv[p]; w = g_wv[p]; }
        while (p < p1) {
            int pn = p + 1;
            int sn2 = 0; float wn = 0.0f;
            if (pn < p1) { sn2 = g_srcv[pn]; wn = g_wv[pn]; }
            float4 u = hl4[s * 32 + lane];
            acc.x += w * u.x; acc.y += w * u.y; acc.z += w * u.z; acc.w += w * u.w;
            s = sn2; w = wn; p = pn;
        }
        acc.x = fmaxf(acc.x + bb.x, 0.0f);
        acc.y = fmaxf(acc.y + bb.y, 0.0f);
        acc.z = fmaxf(acc.z + bb.z, 0.0f);
        acc.w = fmaxf(acc.w + bb.w, 0.0f);
        ((float4*)g_t)[i * 32 + lane] = acc;
        ps.x += acc.x; ps.y += acc.y; ps.z += acc.z; ps.w += acc.w;
        pq.x += acc.x * acc.x; pq.y += acc.y * acc.y;
        pq.z += acc.z * acc.z; pq.w += acc.w * acc.w;
    }
    int c = lane * 4;
    float* o1 = g_psum + gw * DIM + c;
    o1[0] = ps.x; o1[1] = ps.y; o1[2] = ps.z; o1[3] = ps.w;
    float* o2 = g_psq + gw * DIM + c;
    o2[0] = pq.x; o2[1] = pq.y; o2[2] = pq.z; o2[3] = pq.w;
}

// ---------------- BN stage 2: per channel, deterministic tree reduction ----------------
__global__ void k_bnstat(const float* __restrict__ gamma, const float* __restrict__ beta) {
    __shared__ float ss[256];
    __shared__ float qq[256];
    int c = blockIdx.x;
    int tid = threadIdx.x;
    float s = 0.0f, q = 0.0f;
    for (int w = tid; w < NWARPS; w += 256) {
        s += g_psum[w * DIM + c];
        q += g_psq[w * DIM + c];
    }
    ss[tid] = s; qq[tid] = q;
    __syncthreads();
    for (int o = 128; o > 0; o >>= 1) {
        if (tid < o) { ss[tid] += ss[tid + o]; qq[tid] += qq[tid + o]; }
        __syncthreads();
    }
    if (tid == 0) {
        float mean = ss[0] / (float)NN;
        float var = qq[0] / (float)NN - mean * mean;
        float istd = rsqrtf(var + BN_EPS);
        float sc = gamma[c] * istd;
        g_scale[c] = sc;
        g_shift[c] = beta[c] - mean * sc;
    }
}

// ---------------- normalize, write next h + xs output ----------------
__global__ void k_norm(float* __restrict__ outxs, int l) {
    int idx = blockIdx.x * blockDim.x + threadIdx.x;  // float4 index
    if (idx >= NN * 32) return;
    int node = idx >> 5, c4 = idx & 31;
    float4 t = ((const float4*)g_t)[idx];
    float4 sc = ((const float4*)g_scale)[c4];
    float4 sh = ((const float4*)g_shift)[c4];
    float4 v;
    v.x = t.x * sc.x + sh.x; v.y = t.y * sc.y + sh.y;
    v.z = t.z * sc.z + sh.z; v.w = t.w * sc.w + sh.w;
    ((float4*)g_h)[idx] = v;
    ((float4*)outxs)[(size_t)node * 96 + l * 32 + c4] = v;
}

// ---------------- pooling: block per graph ----------------
__global__ void k_pool(const float* __restrict__ xs, float* __restrict__ outpool) {
    int g = blockIdx.x;
    int c = threadIdx.x;  // 384
    int a = g_gstart[g], b = g_gstart[g + 1];
    float s = 0.0f;
    for (int i = a; i < b; i++) s += xs[(size_t)i * 384 + c];
    outpool[(size_t)g * 384 + c] = s;
}

// ---------------- launch ----------------
extern "C" void kernel_launch(void* const* d_in, const int* in_sizes, int n_in,
                              void* d_out, int out_size) {
    const float* x = (const float*)d_in[0];
    const int* ei = (const int*)d_in[1];        // int32 (JAX x64 disabled)
    const float* ew = (const float*)d_in[2];
    const int* batch = (const int*)d_in[3];     // int32
    const float* fc_w = (const float*)d_in[4];
    const float* W = (const float*)d_in[5];
    const float* b = (const float*)d_in[6];
    const float* gamma = (const float*)d_in[7];
    const float* beta = (const float*)d_in[8];

    float* out = (float*)d_out;
    float* outpool = out;                    // [512, 384]
    float* outxs = out + (size_t)NG * 384;   // [N, 384]

    const int SMEM_GEMM = 2 * 128 * 129 * sizeof(float);
    cudaFuncSetAttribute(k_gemm, cudaFuncAttributeMaxDynamicSharedMemorySize, SMEM_GEMM);

    float* g_h_p; cudaGetSymbolAddress((void**)&g_h_p, g_h);
    float* g_hl_p; cudaGetSymbolAddress((void**)&g_hl_p, g_hl);

    // preprocessing
    k_zero_cnt<<<(NN + 255) / 256, 256>>>();
    k_hist<<<(EE + 255) / 256, 256>>>(ei);
    k_scan<<<1, 1024>>>();
    k_sort<<<(EE + 255) / 256, 256>>>(ei, ew);
    k_dinv<<<(NN + 255) / 256, 256>>>();
    k_coef<<<(NN + 255) / 256, 256>>>();
    k_gstart<<<(NN + 255) / 256, 256>>>(batch);

    const int GEMM_GRID = (NN + 127) / 128;

    // h0 = x @ fc_w^T
    k_gemm<<<GEMM_GRID, 256, SMEM_GEMM>>>(x, fc_w, g_h_p, NN);

    for (int l = 0; l < NLAYER; l++) {
        k_gemm<<<GEMM_GRID, 256, SMEM_GEMM>>>(g_h_p, W + (size_t)l * DIM * DIM, g_hl_p, NN);
        k_agg<<<AGG_BLOCKS, 256>>>(b + l * DIM);
        k_bnstat<<<DIM, 256>>>(gamma + l * DIM, beta + l * DIM);
        k_norm<<<(NN * 32 + 255) / 256, 256>>>(outxs, l);
    }

    k_pool<<<NG, 384>>>(outxs, outpool);
}

// round 8
// speedup vs baseline: 1.1945x; 1.1945x over previous
#include <cuda_runtime.h>
#include <cuda_bf16.h>
#include <cstdint>

#define NN 100000
#define EE 1600000
#define DIM 128
#define NG 512
#define NLAYER 3
#define AGG_BLOCKS 1024
#define NWARPS (AGG_BLOCKS * 8)
#define BN_EPS 1e-5f

// ---------------- scratch (static device memory; no allocations) ----------------
__device__ float g_h[NN * DIM];        // current features
__device__ float g_hl[NN * DIM];       // GEMM output
__device__ float g_t[NN * DIM];        // pre-BN (post relu) values
__device__ float g_dinv[NN];
__device__ int   g_cnt[NN];
__device__ int   g_off[NN + 1];
__device__ int   g_cur[NN];
__device__ int   g_srcv[EE];           // sorted-by-dst source node ids
__device__ float g_wv[EE];             // sorted edge weights, later fused norm coeffs
__device__ float g_psum[NWARPS * DIM];
__device__ float g_psq[NWARPS * DIM];
__device__ float g_scale[DIM];
__device__ float g_shift[DIM];
__device__ int   g_gstart[NG + 1];

// ---------------- preprocessing kernels ----------------
__global__ void k_zero_cnt() {
    int i = blockIdx.x * blockDim.x + threadIdx.x;
    if (i < NN) g_cnt[i] = 0;
}

__global__ void k_hist(const int* __restrict__ ei) {
    int e = blockIdx.x * blockDim.x + threadIdx.x;
    if (e < EE) {
        int c = ei[EE + e];  // col = destination
        atomicAdd(&g_cnt[c], 1);
    }
}

// single-block exclusive scan of g_cnt -> g_off, g_cur (1024 threads)
__global__ void k_scan() {
    __shared__ int warpsum[32];
    int tid = threadIdx.x;
    const int CH = (NN + 1023) / 1024;  // 98
    int start = tid * CH;
    int end = min(start + CH, NN);
    int s = 0;
    for (int i = start; i < end; i++) s += g_cnt[i];
    int lane = tid & 31, wid = tid >> 5;
    int incl = s;
    #pragma unroll
    for (int o = 1; o < 32; o <<= 1) {
        int v = __shfl_up_sync(0xFFFFFFFFu, incl, o);
        if (lane >= o) incl += v;
    }
    if (lane == 31) warpsum[wid] = incl;
    __syncthreads();
    if (wid == 0) {
        int v = warpsum[lane];
        #pragma unroll
        for (int o = 1; o < 32; o <<= 1) {
            int u = __shfl_up_sync(0xFFFFFFFFu, v, o);
            if (lane >= o) v += u;
        }
        warpsum[lane] = v;
    }
    __syncthreads();
    int base = (incl - s) + (wid > 0 ? warpsum[wid - 1] : 0);
    int run = base;
    for (int i = start; i < end; i++) {
        int cv = g_cnt[i];
        g_off[i] = run;
        g_cur[i] = run;
        run += cv;
    }
    if (tid == 1023) g_off[NN] = base;  // tail chunk always empty
}

__global__ void k_sort(const int* __restrict__ ei, const float* __restrict__ ew) {
    int e = blockIdx.x * blockDim.x + threadIdx.x;
    if (e < EE) {
        int d = ei[EE + e];
        int p = atomicAdd(&g_cur[d], 1);
        g_srcv[p] = ei[e];
        g_wv[p] = ew[e];
    }
}

__global__ void k_dinv() {
    int i = blockIdx.x * blockDim.x + threadIdx.x;
    if (i >= NN) return;
    float s = 1.0f;  // self-loop weight
    int p1 = g_off[i + 1];
    for (int p = g_off[i]; p < p1; p++) s += g_wv[p];
    g_dinv[i] = rsqrtf(s);
}

__global__ void k_coef() {
    int i = blockIdx.x * blockDim.x + threadIdx.x;
    if (i >= NN) return;
    float di = g_dinv[i];
    int p1 = g_off[i + 1];
    for (int p = g_off[i]; p < p1; p++)
        g_wv[p] = g_dinv[g_srcv[p]] * g_wv[p] * di;
}

__global__ void k_gstart(const int* __restrict__ batch) {
    int i = blockIdx.x * blockDim.x + threadIdx.x;
    if (i >= NN) return;
    int b = batch[i];
    int pb = (i == 0) ? -1 : batch[i - 1];
    for (int g = pb + 1; g <= b; g++) g_gstart[g] = i;
    if (i == NN - 1)
        for (int g = b + 1; g <= NG; g++) g_gstart[g] = NN;
}

// ================= tensor-core GEMM via mma.sync (HMMA, sm_80 PTX) ==============
// C[i][o] = sum_k A[i][k] * Wg[o*128+k], fp32 via 2-way bf16 split:
//   a = ah + al;  C = Ah*Bh + Ah*Bl + Al*Bh   (missing term ~2^-18, err ~1e-5)
// CTA tile 128x128, 8 warps, warp tile 32x64. Smem bf16 tiles, chunk^row swizzle.

__device__ __forceinline__ uint32_t smem_u32(const void* p) {
    uint32_t a;
    asm("{ .reg .u64 t; cvta.to.shared.u64 t, %1; cvt.u32.u64 %0, t; }" : "=r"(a) : "l"(p));
    return a;
}
__device__ __forceinline__ void ldsm4(uint32_t* r, uint32_t a) {
    asm volatile("ldmatrix.sync.aligned.m8n8.x4.shared.b16 {%0,%1,%2,%3}, [%4];"
        : "=r"(r[0]), "=r"(r[1]), "=r"(r[2]), "=r"(r[3]) : "r"(a));
}
__device__ __forceinline__ void mma_bf16(float* c, const uint32_t* a, const uint32_t* b) {
    asm volatile("mma.sync.aligned.m16n8k16.row.col.f32.bf16.bf16.f32 "
        "{%0,%1,%2,%3}, {%4,%5,%6,%7}, {%8,%9}, {%0,%1,%2,%3};"
        : "+f"(c[0]), "+f"(c[1]), "+f"(c[2]), "+f"(c[3])
        : "r"(a[0]), "r"(a[1]), "r"(a[2]), "r"(a[3]), "r"(b[0]), "r"(b[1]));
}
__device__ __forceinline__ uint32_t pack_bf(float x, float y) {
    __nv_bfloat162 t = __floats2bfloat162_rn(x, y);
    return *reinterpret_cast<uint32_t*>(&t);
}

// smem offsets (bytes): Ah, Al, Bh, Bl each 128 rows x 256 B
#define SM_AH 0
#define SM_AL 32768
#define SM_BH 65536
#define SM_BL 98304
#define SMEM_MMA 131072

// byte offset of 16B chunk `c` (0..15) in row `r`, swizzled
__device__ __forceinline__ uint32_t swoff(int r, int c) {
    return (uint32_t)(r * 256 + ((c ^ (r & 7)) << 4));
}

// convert one float4 (4 consecutive cols, col0 = c4*4) into hi/lo bf16x4 at row r
__device__ __forceinline__ void stage4(char* smem, uint32_t offH, uint32_t offL, float4 v) {
    float hx = __bfloat162float(__float2bfloat16(v.x));
    float hy = __bfloat162float(__float2bfloat16(v.y));
    float hz = __bfloat162float(__float2bfloat16(v.z));
    float hw = __bfloat162float(__float2bfloat16(v.w));
    uint2 hp = make_uint2(pack_bf(hx, hy), pack_bf(hz, hw));
    uint2 lp = make_uint2(pack_bf(v.x - hx, v.y - hy), pack_bf(v.z - hz, v.w - hw));
    *reinterpret_cast<uint2*>(smem + offH) = hp;
    *reinterpret_cast<uint2*>(smem + offL) = lp;
}

__global__ void __launch_bounds__(256, 1)
k_gemm_mma(const float* __restrict__ A, const float* __restrict__ Wg,
           float* __restrict__ C, int nrows) {
    extern __shared__ char smem[];
    int tid = threadIdx.x;
    int lane = tid & 31, wid = tid >> 5;
    int row0 = blockIdx.x * 128;

    // ---- stage B (weights) and A tile as split bf16, swizzled ----
    for (int p = tid; p < 4096; p += 256) {         // 128 rows x 32 float4
        int r = p >> 5, c4 = p & 31;
        int chunk = c4 >> 1;
        uint32_t off = swoff(r, chunk) + (c4 & 1) * 8;
        float4 v = ((const float4*)Wg)[p];
        stage4(smem, SM_BH + off, SM_BL + off, v);
    }
    for (int p = tid; p < 4096; p += 256) {
        int r = p >> 5, c4 = p & 31;
        int gr = row0 + r;
        float4 v = (gr < nrows) ? ((const float4*)A)[(size_t)gr * 32 + c4]
                                : make_float4(0.f, 0.f, 0.f, 0.f);
        int chunk = c4 >> 1;
        uint32_t off = swoff(r, chunk) + (c4 & 1) * 8;
        stage4(smem, SM_AH + off, SM_AL + off, v);
    }
    __syncthreads();

    // ---- per-warp tile: rows rowbase..+31, cols nbase..+63 ----
    int rowbase = (wid & 3) * 32;
    int nbase = (wid >> 2) * 64;
    uint32_t sb = smem_u32(smem);

    // per-lane ldmatrix addressing
    int mat = lane >> 3;                 // which 8x8 matrix this lane addresses
    int l7 = lane & 7;
    // A: matrices [m0-7,c0],[m8-15,c0],[m0-7,c1],[m8-15,c1]
    int arow[2]; int axor[2]; uint32_t abyte[2];
    #pragma unroll
    for (int mi = 0; mi < 2; mi++) {
        arow[mi] = rowbase + mi * 16 + (mat & 1) * 8 + l7;
        axor[mi] = arow[mi] & 7;
        abyte[mi] = (uint32_t)(arow[mi] * 256);
    }
    int aco = mat >> 1;
    // B: matrices [n0-7,c0],[n0-7,c1],[n8-15,c0],[n8-15,c1] per n16 group
    int bxor[4]; uint32_t bbyte[4];
    #pragma unroll
    for (int n16 = 0; n16 < 4; n16++) {
        int brow = nbase + n16 * 16 + (mat >> 1) * 8 + l7;
        bxor[n16] = brow & 7;
        bbyte[n16] = (uint32_t)(brow * 256);
    }
    int bco = mat & 1;

    float c[2][8][4];
    #pragma unroll
    for (int mi = 0; mi < 2; mi++)
        #pragma unroll
        for (int nj = 0; nj < 8; nj++)
            #pragma unroll
            for (int q = 0; q < 4; q++) c[mi][nj][q] = 0.0f;

    #pragma unroll 2
    for (int kc = 0; kc < 8; kc++) {
        int c0 = kc * 2;
        uint32_t ah[2][4], al[2][4], bh[4][4], bl[4][4];
        #pragma unroll
        for (int mi = 0; mi < 2; mi++) {
            uint32_t off = abyte[mi] + (((c0 + aco) ^ axor[mi]) << 4);
            ldsm4(ah[mi], sb + SM_AH + off);
            ldsm4(al[mi], sb + SM_AL + off);
        }
        #pragma unroll
        for (int n16 = 0; n16 < 4; n16++) {
            uint32_t off = bbyte[n16] + (((c0 + bco) ^ bxor[n16]) << 4);
            ldsm4(bh[n16], sb + SM_BH + off);
            ldsm4(bl[n16], sb + SM_BL + off);
        }
        #pragma unroll
        for (int mi = 0; mi < 2; mi++) {
            #pragma unroll
            for (int nj = 0; nj < 8; nj++) {
                const uint32_t* bhp = &bh[nj >> 1][(nj & 1) * 2];
                const uint32_t* blp = &bl[nj >> 1][(nj & 1) * 2];
                mma_bf16(c[mi][nj], ah[mi], bhp);
                mma_bf16(c[mi][nj], ah[mi], blp);
                mma_bf16(c[mi][nj], al[mi], bhp);
            }
        }
    }

    // ---- epilogue: direct stores ----
    int gid = lane >> 2, tig = lane & 3;
    #pragma unroll
    for (int mi = 0; mi < 2; mi++) {
        int r_lo = row0 + rowbase + mi * 16 + gid;
        int r_hi = r_lo + 8;
        #pragma unroll
        for (int nj = 0; nj < 8; nj++) {
            int col = nbase + nj * 8 + tig * 2;
            if (r_lo < nrows)
                *reinterpret_cast<float2*>(C + (size_t)r_lo * 128 + col) =
                    make_float2(c[mi][nj][0], c[mi][nj][1]);
            if (r_hi < nrows)
                *reinterpret_cast<float2*>(C + (size_t)r_hi * 128 + col) =
                    make_float2(c[mi][nj][2], c[mi][nj][3]);
        }
    }
}

// ---------------- aggregation: warp per node, CSR gather + bias + relu + BN partials --
__global__ void __launch_bounds__(256)
k_agg(const float* __restrict__ bias) {
    int lane = threadIdx.x & 31;
    int gw = (blockIdx.x * blockDim.x + threadIdx.x) >> 5;
    const float4* hl4 = (const float4*)g_hl;
    float4 bb = *((const float4*)bias + lane);
    float4 ps = make_float4(0, 0, 0, 0);
    float4 pq = make_float4(0, 0, 0, 0);

    for (int i = gw; i < NN; i += NWARPS) {
        float di = g_dinv[i];
        float sn = di * di;
        float4 v = hl4[i * 32 + lane];
        float4 acc;
        acc.x = sn * v.x; acc.y = sn * v.y; acc.z = sn * v.z; acc.w = sn * v.w;
        int p = g_off[i], p1 = g_off[i + 1];
        int s = 0; float w = 0.0f;
        if (p < p1) { s = g_srcv[p]; w = g_wv[p]; }
        while (p < p1) {
            int pn = p + 1;
            int sn2 = 0; float wn = 0.0f;
            if (pn < p1) { sn2 = g_srcv[pn]; wn = g_wv[pn]; }
            float4 u = hl4[s * 32 + lane];
            acc.x += w * u.x; acc.y += w * u.y; acc.z += w * u.z; acc.w += w * u.w;
            s = sn2; w = wn; p = pn;
        }
        acc.x = fmaxf(acc.x + bb.x, 0.0f);
        acc.y = fmaxf(acc.y + bb.y, 0.0f);
        acc.z = fmaxf(acc.z + bb.z, 0.0f);
        acc.w = fmaxf(acc.w + bb.w, 0.0f);
        ((float4*)g_t)[i * 32 + lane] = acc;
        ps.x += acc.x; ps.y += acc.y; ps.z += acc.z; ps.w += acc.w;
        pq.x += acc.x * acc.x; pq.y += acc.y * acc.y;
        pq.z += acc.z * acc.z; pq.w += acc.w * acc.w;
    }
    int c = lane * 4;
    float* o1 = g_psum + gw * DIM + c;
    o1[0] = ps.x; o1[1] = ps.y; o1[2] = ps.z; o1[3] = ps.w;
    float* o2 = g_psq + gw * DIM + c;
    o2[0] = pq.x; o2[1] = pq.y; o2[2] = pq.z; o2[3] = pq.w;
}

// ---------------- BN stage 2: per channel, deterministic tree reduction ----------------
__global__ void k_bnstat(const float* __restrict__ gamma, const float* __restrict__ beta) {
    __shared__ float ss[256];
    __shared__ float qq[256];
    int c = blockIdx.x;
    int tid = threadIdx.x;
    float s = 0.0f, q = 0.0f;
    for (int w = tid; w < NWARPS; w += 256) {
        s += g_psum[w * DIM + c];
        q += g_psq[w * DIM + c];
    }
    ss[tid] = s; qq[tid] = q;
    __syncthreads();
    for (int o = 128; o > 0; o >>= 1) {
        if (tid < o) { ss[tid] += ss[tid + o]; qq[tid] += qq[tid + o]; }
        __syncthreads();
    }
    if (tid == 0) {
        float mean = ss[0] / (float)NN;
        float var = qq[0] / (float)NN - mean * mean;
        float istd = rsqrtf(var + BN_EPS);
        float sc = gamma[c] * istd;
        g_scale[c] = sc;
        g_shift[c] = beta[c] - mean * sc;
    }
}

// ---------------- normalize, write next h + xs output ----------------
__global__ void k_norm(float* __restrict__ outxs, int l) {
    int idx = blockIdx.x * blockDim.x + threadIdx.x;  // float4 index
    if (idx >= NN * 32) return;
    int node = idx >> 5, c4 = idx & 31;
    float4 t = ((const float4*)g_t)[idx];
    float4 sc = ((const float4*)g_scale)[c4];
    float4 sh = ((const float4*)g_shift)[c4];
    float4 v;
    v.x = t.x * sc.x + sh.x; v.y = t.y * sc.y + sh.y;
    v.z = t.z * sc.z + sh.z; v.w = t.w * sc.w + sh.w;
    ((float4*)g_h)[idx] = v;
    ((float4*)outxs)[(size_t)node * 96 + l * 32 + c4] = v;
}

// ---------------- pooling: block per graph ----------------
__global__ void k_pool(const float* __restrict__ xs, float* __restrict__ outpool) {
    int g = blockIdx.x;
    int c = threadIdx.x;  // 384
    int a = g_gstart[g], b = g_gstart[g + 1];
    float s = 0.0f;
    for (int i = a; i < b; i++) s += xs[(size_t)i * 384 + c];
    outpool[(size_t)g * 384 + c] = s;
}

// ---------------- launch ----------------
extern "C" void kernel_launch(void* const* d_in, const int* in_sizes, int n_in,
                              void* d_out, int out_size) {
    const float* x = (const float*)d_in[0];
    const int* ei = (const int*)d_in[1];        // int32 (JAX x64 disabled)
    const float* ew = (const float*)d_in[2];
    const int* batch = (const int*)d_in[3];     // int32
    const float* fc_w = (const float*)d_in[4];
    const float* W = (const float*)d_in[5];
    const float* b = (const float*)d_in[6];
    const float* gamma = (const float*)d_in[7];
    const float* beta = (const float*)d_in[8];

    float* out = (float*)d_out;
    float* outpool = out;                    // [512, 384]
    float* outxs = out + (size_t)NG * 384;   // [N, 384]

    cudaFuncSetAttribute(k_gemm_mma, cudaFuncAttributeMaxDynamicSharedMemorySize, SMEM_MMA);

    float* g_h_p; cudaGetSymbolAddress((void**)&g_h_p, g_h);
    float* g_hl_p; cudaGetSymbolAddress((void**)&g_hl_p, g_hl);

    // preprocessing
    k_zero_cnt<<<(NN + 255) / 256, 256>>>();
    k_hist<<<(EE + 255) / 256, 256>>>(ei);
    k_scan<<<1, 1024>>>();
    k_sort<<<(EE + 255) / 256, 256>>>(ei, ew);
    k_dinv<<<(NN + 255) / 256, 256>>>();
    k_coef<<<(NN + 255) / 256, 256>>>();
    k_gstart<<<(NN + 255) / 256, 256>>>(batch);

    const int GEMM_GRID = (NN + 127) / 128;  // 782

    // h0 = x @ fc_w^T
    k_gemm_mma<<<GEMM_GRID, 256, SMEM_MMA>>>(x, fc_w, g_h_p, NN);

    for (int l = 0; l < NLAYER; l++) {
        k_gemm_mma<<<GEMM_GRID, 256, SMEM_MMA>>>(g_h_p, W + (size_t)l * DIM * DIM, g_hl_p, NN);
        k_agg<<<AGG_BLOCKS, 256>>>(b + l * DIM);
        k_bnstat<<<DIM, 256>>>(gamma + l * DIM, beta + l * DIM);
        k_norm<<<(NN * 32 + 255) / 256, 256>>>(outxs, l);
    }

    k_pool<<<NG, 384>>>(outxs, outpool);
}

// round 9
// speedup vs baseline: 1.5640x; 1.3094x over previous
#include <cuda_runtime.h>
#include <cuda_bf16.h>
#include <cstdint>

#define NN 100000
#define EE 1600000
#define DIM 128
#define NG 512
#define NLAYER 3
#define NTILES ((NN + 127) / 128)      // 782
#define PADROWS (NTILES * 128)         // 100096
#define AGG_BLOCKS 1024
#define NWARPS (AGG_BLOCKS * 8)
#define BN_EPS 1e-5f

// ---------------- scratch (static device memory; no allocations) ----------------
__device__ __align__(16) __nv_bfloat16 g_ah[PADROWS * DIM];  // activation hi split (swizzled)
__device__ __align__(16) __nv_bfloat16 g_al[PADROWS * DIM];  // activation lo split (swizzled)
__device__ __align__(16) __nv_bfloat16 g_wh[4 * DIM * DIM];  // weight hi (fc + 3 layers, swizzled)
__device__ __align__(16) __nv_bfloat16 g_wl[4 * DIM * DIM];  // weight lo
__device__ float g_hl[NN * DIM];       // GEMM output (fp32, for aggregation)
__device__ float g_t[NN * DIM];        // pre-BN (post relu) values
__device__ float g_dinv[NN];
__device__ int   g_cnt[NN];
__device__ int   g_off[NN + 1];
__device__ int   g_cur[NN];
__device__ int   g_srcv[EE];           // sorted-by-dst source node ids
__device__ float g_wv[EE];             // sorted edge weights, later fused norm coeffs
__device__ float g_psum[NWARPS * DIM];
__device__ float g_psq[NWARPS * DIM];
__device__ float g_scale[DIM];
__device__ float g_shift[DIM];
__device__ int   g_gstart[NG + 1];

// ---------------- helpers ----------------
__device__ __forceinline__ uint32_t smem_u32(const void* p) {
    uint32_t a;
    asm("{ .reg .u64 t; cvta.to.shared.u64 t, %1; cvt.u32.u64 %0, t; }" : "=r"(a) : "l"(p));
    return a;
}
__device__ __forceinline__ void ldsm4(uint32_t* r, uint32_t a) {
    asm volatile("ldmatrix.sync.aligned.m8n8.x4.shared.b16 {%0,%1,%2,%3}, [%4];"
        : "=r"(r[0]), "=r"(r[1]), "=r"(r[2]), "=r"(r[3]) : "r"(a));
}
__device__ __forceinline__ void mma_bf16(float* c, const uint32_t* a, const uint32_t* b) {
    asm volatile("mma.sync.aligned.m16n8k16.row.col.f32.bf16.bf16.f32 "
        "{%0,%1,%2,%3}, {%4,%5,%6,%7}, {%8,%9}, {%0,%1,%2,%3};"
        : "+f"(c[0]), "+f"(c[1]), "+f"(c[2]), "+f"(c[3])
        : "r"(a[0]), "r"(a[1]), "r"(a[2]), "r"(a[3]), "r"(b[0]), "r"(b[1]));
}
__device__ __forceinline__ uint32_t pack_bf(float x, float y) {
    __nv_bfloat162 t = __floats2bfloat162_rn(x, y);
    return *reinterpret_cast<uint32_t*>(&t);
}
__device__ __forceinline__ void cp16(uint32_t dst, const void* src) {
    asm volatile("cp.async.cg.shared.global [%0], [%1], 16;" :: "r"(dst), "l"(src));
}
__device__ __forceinline__ void cp_commit_wait() {
    asm volatile("cp.async.commit_group;" ::: "memory");
    asm volatile("cp.async.wait_group 0;" ::: "memory");
}

// swizzled byte offset of bf16 column pair group within a row (global row r ok: tiles 128-aligned)
// c4 = group of 4 bf16 cols (col0 = 4*c4)
__device__ __forceinline__ uint32_t sw_addr(int r, int c4) {
    int chunk = c4 >> 1;
    return (uint32_t)r * 256u + (uint32_t)(((chunk ^ (r & 7)) << 4) + (c4 & 1) * 8);
}
// split a float4 into hi/lo bf16x2 pairs
__device__ __forceinline__ void split4(float4 v, uint2& hp, uint2& lp) {
    float hx = __bfloat162float(__float2bfloat16(v.x));
    float hy = __bfloat162float(__float2bfloat16(v.y));
    float hz = __bfloat162float(__float2bfloat16(v.z));
    float hw = __bfloat162float(__float2bfloat16(v.w));
    hp = make_uint2(pack_bf(hx, hy), pack_bf(hz, hw));
    lp = make_uint2(pack_bf(v.x - hx, v.y - hy), pack_bf(v.z - hz, v.w - hw));
}

// ---------------- weight convert: fc_w + W[3] -> swizzled bf16 splits ----------------
__global__ void k_cvtw(const float* __restrict__ fcw, const float* __restrict__ W) {
    int p = blockIdx.x * blockDim.x + threadIdx.x;   // 4*128*32 float4s
    if (p >= 4 * 128 * 32) return;
    int layer = p >> 12, rem = p & 4095;
    int o = rem >> 5, c4 = rem & 31;
    const float* src = (layer == 0) ? fcw : (W + (size_t)(layer - 1) * DIM * DIM);
    float4 v = ((const float4*)src)[o * 32 + c4];
    uint2 hp, lp; split4(v, hp, lp);
    uint32_t off = (uint32_t)layer * 32768u + sw_addr(o, c4);
    *reinterpret_cast<uint2*>((char*)g_wh + off) = hp;
    *reinterpret_cast<uint2*>((char*)g_wl + off) = lp;
}

// ---------------- x convert: fp32 -> swizzled bf16 splits (zero pad rows) ----------------
__global__ void k_cvt(const float* __restrict__ x) {
    int p = blockIdx.x * blockDim.x + threadIdx.x;   // PADROWS*32 float4s
    if (p >= PADROWS * 32) return;
    int r = p >> 5, c4 = p & 31;
    float4 v = (r < NN) ? ((const float4*)x)[(size_t)r * 32 + c4]
                        : make_float4(0.f, 0.f, 0.f, 0.f);
    uint2 hp, lp; split4(v, hp, lp);
    uint32_t off = sw_addr(r, c4);
    *reinterpret_cast<uint2*>((char*)g_ah + off) = hp;
    *reinterpret_cast<uint2*>((char*)g_al + off) = lp;
}

// ================= tensor-core GEMM via mma.sync (HMMA) ==============
// C[i][o] = sum_k A[i][k]*Wg[o*128+k]; fp32 via split: Ah*Bh + Ah*Bl + Al*Bh.
// Inputs pre-split & pre-swizzled in gmem; staging = pure cp.async copy.
// MODE 0: write fp32 C. MODE 1: write split bf16 back to g_ah/g_al (in-place rows).
#define SM_AH 0
#define SM_AL 32768
#define SM_BH 65536
#define SM_BL 98304
#define SMEM_MMA 131072

template<int MODE>
__global__ void __launch_bounds__(256, 1)
k_gemm_mma(const __nv_bfloat16* __restrict__ Bh_g, const __nv_bfloat16* __restrict__ Bl_g,
           float* __restrict__ C, int nrows) {
    extern __shared__ char smem[];
    uint32_t sb = smem_u32(smem);
    int tid = threadIdx.x;
    int lane = tid & 31, wid = tid >> 5;
    int row0 = blockIdx.x * 128;

    // ---- stage 128KB via cp.async: A hi/lo (tile rows), B hi/lo ----
    {
        const char* aH = (const char*)g_ah + (size_t)row0 * 256;
        const char* aL = (const char*)g_al + (size_t)row0 * 256;
        const char* bH = (const char*)Bh_g;
        const char* bL = (const char*)Bl_g;
        uint32_t t16 = tid * 16;
        #pragma unroll
        for (int j = 0; j < 8; j++) {
            uint32_t o = t16 + j * 4096;
            cp16(sb + SM_AH + o, aH + o);
            cp16(sb + SM_AL + o, aL + o);
            cp16(sb + SM_BH + o, bH + o);
            cp16(sb + SM_BL + o, bL + o);
        }
        cp_commit_wait();
    }
    __syncthreads();

    // ---- per-warp tile: rows rowbase..+31, cols nbase..+63 ----
    int rowbase = (wid & 3) * 32;
    int nbase = (wid >> 2) * 64;

    int mat = lane >> 3;
    int l7 = lane & 7;
    int arow[2]; int axor[2]; uint32_t abyte[2];
    #pragma unroll
    for (int mi = 0; mi < 2; mi++) {
        arow[mi] = rowbase + mi * 16 + (mat & 1) * 8 + l7;
        axor[mi] = arow[mi] & 7;
        abyte[mi] = (uint32_t)(arow[mi] * 256);
    }
    int aco = mat >> 1;
    int bxor[4]; uint32_t bbyte[4];
    #pragma unroll
    for (int n16 = 0; n16 < 4; n16++) {
        int brow = nbase + n16 * 16 + (mat >> 1) * 8 + l7;
        bxor[n16] = brow & 7;
        bbyte[n16] = (uint32_t)(brow * 256);
    }
    int bco = mat & 1;

    float c[2][8][4];
    #pragma unroll
    for (int mi = 0; mi < 2; mi++)
        #pragma unroll
        for (int nj = 0; nj < 8; nj++)
            #pragma unroll
            for (int q = 0; q < 4; q++) c[mi][nj][q] = 0.0f;

    #pragma unroll 2
    for (int kc = 0; kc < 8; kc++) {
        int c0 = kc * 2;
        uint32_t ah[2][4], al[2][4], bh[4][4], bl[4][4];
        #pragma unroll
        for (int mi = 0; mi < 2; mi++) {
            uint32_t off = abyte[mi] + (((c0 + aco) ^ axor[mi]) << 4);
            ldsm4(ah[mi], sb + SM_AH + off);
            ldsm4(al[mi], sb + SM_AL + off);
        }
        #pragma unroll
        for (int n16 = 0; n16 < 4; n16++) {
            uint32_t off = bbyte[n16] + (((c0 + bco) ^ bxor[n16]) << 4);
            ldsm4(bh[n16], sb + SM_BH + off);
            ldsm4(bl[n16], sb + SM_BL + off);
        }
        #pragma unroll
        for (int mi = 0; mi < 2; mi++) {
            #pragma unroll
            for (int nj = 0; nj < 8; nj++) {
                const uint32_t* bhp = &bh[nj >> 1][(nj & 1) * 2];
                const uint32_t* blp = &bl[nj >> 1][(nj & 1) * 2];
                mma_bf16(c[mi][nj], ah[mi], bhp);
                mma_bf16(c[mi][nj], ah[mi], blp);
                mma_bf16(c[mi][nj], al[mi], bhp);
            }
        }
    }

    // ---- epilogue ----
    int gid = lane >> 2, tig = lane & 3;
    #pragma unroll
    for (int mi = 0; mi < 2; mi++) {
        int r_lo = row0 + rowbase + mi * 16 + gid;
        int r_hi = r_lo + 8;
        #pragma unroll
        for (int nj = 0; nj < 8; nj++) {
            int col = nbase + nj * 8 + tig * 2;   // even column
            if (MODE == 0) {
                if (r_lo < nrows)
                    *reinterpret_cast<float2*>(C + (size_t)r_lo * 128 + col) =
                        make_float2(c[mi][nj][0], c[mi][nj][1]);
                if (r_hi < nrows)
                    *reinterpret_cast<float2*>(C + (size_t)r_hi * 128 + col) =
                        make_float2(c[mi][nj][2], c[mi][nj][3]);
            } else {
                int chunk = col >> 3;
                uint32_t inrow = (uint32_t)((col & 7) * 2);
                if (r_lo < nrows) {
                    float v0 = c[mi][nj][0], v1 = c[mi][nj][1];
                    float h0 = __bfloat162float(__float2bfloat16(v0));
                    float h1 = __bfloat162float(__float2bfloat16(v1));
                    uint32_t off = (uint32_t)r_lo * 256u + (((chunk ^ (r_lo & 7)) << 4) + inrow);
                    *reinterpret_cast<uint32_t*>((char*)g_ah + off) = pack_bf(h0, h1);
                    *reinterpret_cast<uint32_t*>((char*)g_al + off) = pack_bf(v0 - h0, v1 - h1);
                }
                if (r_hi < nrows) {
                    float v0 = c[mi][nj][2], v1 = c[mi][nj][3];
                    float h0 = __bfloat162float(__float2bfloat16(v0));
                    float h1 = __bfloat162float(__float2bfloat16(v1));
                    uint32_t off = (uint32_t)r_hi * 256u + (((chunk ^ (r_hi & 7)) << 4) + inrow);
                    *reinterpret_cast<uint32_t*>((char*)g_ah + off) = pack_bf(h0, h1);
                    *reinterpret_cast<uint32_t*>((char*)g_al + off) = pack_bf(v0 - h0, v1 - h1);
                }
            }
        }
    }
}

// ---------------- preprocessing kernels ----------------
__global__ void k_zero_cnt() {
    int i = blockIdx.x * blockDim.x + threadIdx.x;
    if (i < NN) g_cnt[i] = 0;
}

__global__ void k_hist(const int* __restrict__ ei) {
    int e = blockIdx.x * blockDim.x + threadIdx.x;
    if (e < EE) {
        int c = ei[EE + e];  // col = destination
        atomicAdd(&g_cnt[c], 1);
    }
}

// single-block exclusive scan of g_cnt -> g_off, g_cur (1024 threads)
__global__ void k_scan() {
    __shared__ int warpsum[32];
    int tid = threadIdx.x;
    const int CH = (NN + 1023) / 1024;  // 98
    int start = tid * CH;
    int end = min(start + CH, NN);
    int s = 0;
    for (int i = start; i < end; i++) s += g_cnt[i];
    int lane = tid & 31, wid = tid >> 5;
    int incl = s;
    #pragma unroll
    for (int o = 1; o < 32; o <<= 1) {
        int v = __shfl_up_sync(0xFFFFFFFFu, incl, o);
        if (lane >= o) incl += v;
    }
    if (lane == 31) warpsum[wid] = incl;
    __syncthreads();
    if (wid == 0) {
        int v = warpsum[lane];
        #pragma unroll
        for (int o = 1; o < 32; o <<= 1) {
            int u = __shfl_up_sync(0xFFFFFFFFu, v, o);
            if (lane >= o) v += u;
        }
        warpsum[lane] = v;
    }
    __syncthreads();
    int base = (incl - s) + (wid > 0 ? warpsum[wid - 1] : 0);
    int run = base;
    for (int i = start; i < end; i++) {
        int cv = g_cnt[i];
        g_off[i] = run;
        g_cur[i] = run;
        run += cv;
    }
    if (tid == 1023) g_off[NN] = base;  // tail chunk always empty
}

__global__ void k_sort(const int* __restrict__ ei, const float* __restrict__ ew) {
    int e = blockIdx.x * blockDim.x + threadIdx.x;
    if (e < EE) {
        int d = ei[EE + e];
        int p = atomicAdd(&g_cur[d], 1);
        g_srcv[p] = ei[e];
        g_wv[p] = ew[e];
    }
}

__global__ void k_dinv() {
    int i = blockIdx.x * blockDim.x + threadIdx.x;
    if (i >= NN) return;
    float s = 1.0f;  // self-loop weight
    int p1 = g_off[i + 1];
    for (int p = g_off[i]; p < p1; p++) s += g_wv[p];
    g_dinv[i] = rsqrtf(s);
}

__global__ void k_coef() {
    int i = blockIdx.x * blockDim.x + threadIdx.x;
    if (i >= NN) return;
    float di = g_dinv[i];
    int p1 = g_off[i + 1];
    for (int p = g_off[i]; p < p1; p++)
        g_wv[p] = g_dinv[g_srcv[p]] * g_wv[p] * di;
}

__global__ void k_gstart(const int* __restrict__ batch) {
    int i = blockIdx.x * blockDim.x + threadIdx.x;
    if (i >= NN) return;
    int b = batch[i];
    int pb = (i == 0) ? -1 : batch[i - 1];
    for (int g = pb + 1; g <= b; g++) g_gstart[g] = i;
    if (i == NN - 1)
        for (int g = b + 1; g <= NG; g++) g_gstart[g] = NN;
}

// ---------------- aggregation: warp per node, CSR gather + bias + relu + BN partials --
__global__ void __launch_bounds__(256)
k_agg(const float* __restrict__ bias) {
    int lane = threadIdx.x & 31;
    int gw = (blockIdx.x * blockDim.x + threadIdx.x) >> 5;
    const float4* hl4 = (const float4*)g_hl;
    float4 bb = *((const float4*)bias + lane);
    float4 ps = make_float4(0, 0, 0, 0);
    float4 pq = make_float4(0, 0, 0, 0);

    for (int i = gw; i < NN; i += NWARPS) {
        float di = g_dinv[i];
        float sn = di * di;
        float4 v = hl4[i * 32 + lane];
        float4 acc;
        acc.x = sn * v.x; acc.y = sn * v.y; acc.z = sn * v.z; acc.w = sn * v.w;
        int p = g_off[i], p1 = g_off[i + 1];
        int s = 0; float w = 0.0f;
        if (p < p1) { s = g_srcv[p]; w = g_wv[p]; }
        while (p < p1) {
            int pn = p + 1;
            int sn2 = 0; float wn = 0.0f;
            if (pn < p1) { sn2 = g_srcv[pn]; wn = g_wv[pn]; }
            float4 u = hl4[s * 32 + lane];
            acc.x += w * u.x; acc.y += w * u.y; acc.z += w * u.z; acc.w += w * u.w;
            s = sn2; w = wn; p = pn;
        }
        acc.x = fmaxf(acc.x + bb.x, 0.0f);
        acc.y = fmaxf(acc.y + bb.y, 0.0f);
        acc.z = fmaxf(acc.z + bb.z, 0.0f);
        acc.w = fmaxf(acc.w + bb.w, 0.0f);
        ((float4*)g_t)[i * 32 + lane] = acc;
        ps.x += acc.x; ps.y += acc.y; ps.z += acc.z; ps.w += acc.w;
        pq.x += acc.x * acc.x; pq.y += acc.y * acc.y;
        pq.z += acc.z * acc.z; pq.w += acc.w * acc.w;
    }
    int c = lane * 4;
    float* o1 = g_psum + gw * DIM + c;
    o1[0] = ps.x; o1[1] = ps.y; o1[2] = ps.z; o1[3] = ps.w;
    float* o2 = g_psq + gw * DIM + c;
    o2[0] = pq.x; o2[1] = pq.y; o2[2] = pq.z; o2[3] = pq.w;
}

// ---------------- BN stage 2: per channel, deterministic tree reduction ----------------
__global__ void k_bnstat(const float* __restrict__ gamma, const float* __restrict__ beta) {
    __shared__ float ss[256];
    __shared__ float qq[256];
    int c = blockIdx.x;
    int tid = threadIdx.x;
    float s = 0.0f, q = 0.0f;
    for (int w = tid; w < NWARPS; w += 256) {
        s += g_psum[w * DIM + c];
        q += g_psq[w * DIM + c];
    }
    ss[tid] = s; qq[tid] = q;
    __syncthreads();
    for (int o = 128; o > 0; o >>= 1) {
        if (tid < o) { ss[tid] += ss[tid + o]; qq[tid] += qq[tid + o]; }
        __syncthreads();
    }
    if (tid == 0) {
        float mean = ss[0] / (float)NN;
        float var = qq[0] / (float)NN - mean * mean;
        float istd = rsqrtf(var + BN_EPS);
        float sc = gamma[c] * istd;
        g_scale[c] = sc;
        g_shift[c] = beta[c] - mean * sc;
    }
}

// ---------------- normalize: write xs output + split bf16 for next GEMM ----------------
__global__ void k_norm(float* __restrict__ outxs, int l) {
    int idx = blockIdx.x * blockDim.x + threadIdx.x;  // float4 index
    if (idx >= NN * 32) return;
    int node = idx >> 5, c4 = idx & 31;
    float4 t = ((const float4*)g_t)[idx];
    float4 sc = ((const float4*)g_scale)[c4];
    float4 sh = ((const float4*)g_shift)[c4];
    float4 v;
    v.x = t.x * sc.x + sh.x; v.y = t.y * sc.y + sh.y;
    v.z = t.z * sc.z + sh.z; v.w = t.w * sc.w + sh.w;
    ((float4*)outxs)[(size_t)node * 96 + l * 32 + c4] = v;
    uint2 hp, lp; split4(v, hp, lp);
    uint32_t off = sw_addr(node, c4);
    *reinterpret_cast<uint2*>((char*)g_ah + off) = hp;
    *reinterpret_cast<uint2*>((char*)g_al + off) = lp;
}

// ---------------- pooling: block per graph ----------------
__global__ void k_pool(const float* __restrict__ xs, float* __restrict__ outpool) {
    int g = blockIdx.x;
    int c = threadIdx.x;  // 384
    int a = g_gstart[g], b = g_gstart[g + 1];
    float s = 0.0f;
    for (int i = a; i < b; i++) s += xs[(size_t)i * 384 + c];
    outpool[(size_t)g * 384 + c] = s;
}

// ---------------- launch ----------------
extern "C" void kernel_launch(void* const* d_in, const int* in_sizes, int n_in,
                              void* d_out, int out_size) {
    const float* x = (const float*)d_in[0];
    const int* ei = (const int*)d_in[1];        // int32 (JAX x64 disabled)
    const float* ew = (const float*)d_in[2];
    const int* batch = (const int*)d_in[3];     // int32
    const float* fc_w = (const float*)d_in[4];
    const float* W = (const float*)d_in[5];
    const float* b = (const float*)d_in[6];
    const float* gamma = (const float*)d_in[7];
    const float* beta = (const float*)d_in[8];

    float* out = (float*)d_out;
    float* outpool = out;                    // [512, 384]
    float* outxs = out + (size_t)NG * 384;   // [N, 384]

    cudaFuncSetAttribute(k_gemm_mma<0>, cudaFuncAttributeMaxDynamicSharedMemorySize, SMEM_MMA);
    cudaFuncSetAttribute(k_gemm_mma<1>, cudaFuncAttributeMaxDynamicSharedMemorySize, SMEM_MMA);

    float* g_hl_p; cudaGetSymbolAddress((void**)&g_hl_p, g_hl);
    __nv_bfloat16* g_wh_p; cudaGetSymbolAddress((void**)&g_wh_p, g_wh);
    __nv_bfloat16* g_wl_p; cudaGetSymbolAddress((void**)&g_wl_p, g_wl);

    // convert weights + x, then the two graph-independent GEMMs first
    k_cvtw<<<(4 * 128 * 32 + 255) / 256, 256>>>(fc_w, W);
    k_cvt<<<(PADROWS * 32 + 255) / 256, 256>>>(x);
    // h0 = x @ fc_w^T  (writes split bf16 in place)
    k_gemm_mma<1><<<NTILES, 256, SMEM_MMA>>>(g_wh_p, g_wl_p, nullptr, NN);
    // layer 0 linear: hl = h0 @ W0^T (fp32 out)
    k_gemm_mma<0><<<NTILES, 256, SMEM_MMA>>>(g_wh_p + 16384, g_wl_p + 16384, g_hl_p, NN);

    // CSR preprocessing
    k_zero_cnt<<<(NN + 255) / 256, 256>>>();
    k_hist<<<(EE + 255) / 256, 256>>>(ei);
    k_scan<<<1, 1024>>>();
    k_sort<<<(EE + 255) / 256, 256>>>(ei, ew);
    k_dinv<<<(NN + 255) / 256, 256>>>();
    k_coef<<<(NN + 255) / 256, 256>>>();
    k_gstart<<<(NN + 255) / 256, 256>>>(batch);

    for (int l = 0; l < NLAYER; l++) {
        if (l > 0)  // layer-l linear from previous norm output
            k_gemm_mma<0><<<NTILES, 256, SMEM_MMA>>>(g_wh_p + (l + 1) * 16384,
                                                     g_wl_p + (l + 1) * 16384, g_hl_p, NN);
        k_agg<<<AGG_BLOCKS, 256>>>(b + l * DIM);
        k_bnstat<<<DIM, 256>>>(gamma + l * DIM, beta + l * DIM);
        k_norm<<<(NN * 32 + 255) / 256, 256>>>(outxs, l);
    }

    k_pool<<<NG, 384>>>(outxs, outpool);
}

// round 10
// speedup vs baseline: 1.6793x; 1.0737x over previous
#include <cuda_runtime.h>
#include <cuda_bf16.h>
#include <cstdint>

#define NN 100000
#define EE 1600000
#define DIM 128
#define NG 512
#define NLAYER 3
#define NT64 ((NN + 63) / 64)          // 1563 gemm tiles
#define PADROWS 100096                  // multiple of 128 (and 64), >= NN
#define AGG_BLOCKS 1024
#define NWARPS (AGG_BLOCKS * 8)
#define BN_EPS 1e-5f

// ---------------- scratch (static device memory; no allocations) ----------------
__device__ __align__(16) __nv_bfloat16 g_ah[PADROWS * DIM];  // activation hi split (swizzled)
__device__ __align__(16) __nv_bfloat16 g_al[PADROWS * DIM];  // activation lo split (swizzled)
__device__ __align__(16) __nv_bfloat16 g_wh[4 * DIM * DIM];  // weight hi (fc + 3 layers, swizzled)
__device__ __align__(16) __nv_bfloat16 g_wl[4 * DIM * DIM];  // weight lo
__device__ float g_hl[NN * DIM];       // GEMM output (fp32, for aggregation)
__device__ float g_t[NN * DIM];        // pre-BN (post relu) values
__device__ float g_dinv[NN];
__device__ int   g_cnt[NN];
__device__ int   g_off[NN + 1];
__device__ int   g_cur[NN];
__device__ int   g_srcv[EE];           // sorted-by-dst source node ids
__device__ float g_wv[EE];             // sorted edge weights, later fused norm coeffs
__device__ float g_psum[NWARPS * DIM];
__device__ float g_psq[NWARPS * DIM];
__device__ float g_scale[DIM];
__device__ float g_shift[DIM];
__device__ int   g_gstart[NG + 1];

// ---------------- helpers ----------------
__device__ __forceinline__ uint32_t smem_u32(const void* p) {
    uint32_t a;
    asm("{ .reg .u64 t; cvta.to.shared.u64 t, %1; cvt.u32.u64 %0, t; }" : "=r"(a) : "l"(p));
    return a;
}
__device__ __forceinline__ void ldsm4(uint32_t* r, uint32_t a) {
    asm volatile("ldmatrix.sync.aligned.m8n8.x4.shared.b16 {%0,%1,%2,%3}, [%4];"
        : "=r"(r[0]), "=r"(r[1]), "=r"(r[2]), "=r"(r[3]) : "r"(a));
}
__device__ __forceinline__ void mma_bf16(float* c, const uint32_t* a, const uint32_t* b) {
    asm volatile("mma.sync.aligned.m16n8k16.row.col.f32.bf16.bf16.f32 "
        "{%0,%1,%2,%3}, {%4,%5,%6,%7}, {%8,%9}, {%0,%1,%2,%3};"
        : "+f"(c[0]), "+f"(c[1]), "+f"(c[2]), "+f"(c[3])
        : "r"(a[0]), "r"(a[1]), "r"(a[2]), "r"(a[3]), "r"(b[0]), "r"(b[1]));
}
__device__ __forceinline__ uint32_t pack_bf(float x, float y) {
    __nv_bfloat162 t = __floats2bfloat162_rn(x, y);
    return *reinterpret_cast<uint32_t*>(&t);
}
__device__ __forceinline__ void cp16(uint32_t dst, const void* src) {
    asm volatile("cp.async.cg.shared.global [%0], [%1], 16;" :: "r"(dst), "l"(src));
}
__device__ __forceinline__ void cp_commit_wait() {
    asm volatile("cp.async.commit_group;" ::: "memory");
    asm volatile("cp.async.wait_group 0;" ::: "memory");
}

// swizzled byte offset (global row r; tiles are 64/128-row aligned so (r&7) is layout-stable)
__device__ __forceinline__ uint32_t sw_addr(int r, int c4) {
    int chunk = c4 >> 1;
    return (uint32_t)r * 256u + (uint32_t)(((chunk ^ (r & 7)) << 4) + (c4 & 1) * 8);
}
__device__ __forceinline__ void split4(float4 v, uint2& hp, uint2& lp) {
    float hx = __bfloat162float(__float2bfloat16(v.x));
    float hy = __bfloat162float(__float2bfloat16(v.y));
    float hz = __bfloat162float(__float2bfloat16(v.z));
    float hw = __bfloat162float(__float2bfloat16(v.w));
    hp = make_uint2(pack_bf(hx, hy), pack_bf(hz, hw));
    lp = make_uint2(pack_bf(v.x - hx, v.y - hy), pack_bf(v.z - hz, v.w - hw));
}

// ---------------- fused convert: x (+pad) AND all weights -> swizzled bf16 splits ----
#define CVT_XP (PADROWS * 32)
__global__ void k_cvtall(const float* __restrict__ x, const float* __restrict__ fcw,
                         const float* __restrict__ W) {
    int p = blockIdx.x * blockDim.x + threadIdx.x;
    if (p < CVT_XP) {
        int r = p >> 5, c4 = p & 31;
        float4 v = (r < NN) ? ((const float4*)x)[(size_t)r * 32 + c4]
                            : make_float4(0.f, 0.f, 0.f, 0.f);
        uint2 hp, lp; split4(v, hp, lp);
        uint32_t off = sw_addr(r, c4);
        *reinterpret_cast<uint2*>((char*)g_ah + off) = hp;
        *reinterpret_cast<uint2*>((char*)g_al + off) = lp;
    } else {
        int q = p - CVT_XP;
        if (q >= 4 * 128 * 32) return;
        int layer = q >> 12, rem = q & 4095;
        int o = rem >> 5, c4 = rem & 31;
        const float* src = (layer == 0) ? fcw : (W + (size_t)(layer - 1) * DIM * DIM);
        float4 v = ((const float4*)src)[o * 32 + c4];
        uint2 hp, lp; split4(v, hp, lp);
        uint32_t off = (uint32_t)layer * 32768u + sw_addr(o, c4);
        *reinterpret_cast<uint2*>((char*)g_wh + off) = hp;
        *reinterpret_cast<uint2*>((char*)g_wl + off) = lp;
    }
}

// ================= tensor-core GEMM via mma.sync (HMMA) ==============
// 64x128 CTA tile, 96KB smem, 2 CTAs/SM. Warp tile 32x32 (2x4 warps).
// fp32 via split: Ah*Bh + Ah*Bl + Al*Bh. Inputs pre-split & pre-swizzled.
// MODE 0: write fp32 C. MODE 1: write split bf16 back to g_ah/g_al.
#define SM_AH 0
#define SM_AL 16384
#define SM_BH 32768
#define SM_BL 65536
#define SMEM_MMA 98304

template<int MODE>
__global__ void __launch_bounds__(256, 2)
k_gemm_mma(const __nv_bfloat16* __restrict__ Bh_g, const __nv_bfloat16* __restrict__ Bl_g,
           float* __restrict__ C, int nrows) {
    extern __shared__ char smem[];
    uint32_t sb = smem_u32(smem);
    int tid = threadIdx.x;
    int lane = tid & 31, wid = tid >> 5;
    int row0 = blockIdx.x * 64;

    // ---- stage 96KB via cp.async: A hi/lo (64 rows = 16KB each), B hi/lo (32KB each) --
    {
        const char* aH = (const char*)g_ah + (size_t)row0 * 256;
        const char* aL = (const char*)g_al + (size_t)row0 * 256;
        const char* bH = (const char*)Bh_g;
        const char* bL = (const char*)Bl_g;
        uint32_t t16 = tid * 16;
        #pragma unroll
        for (int j = 0; j < 4; j++) {
            uint32_t o = t16 + j * 4096;
            cp16(sb + SM_AH + o, aH + o);
            cp16(sb + SM_AL + o, aL + o);
        }
        #pragma unroll
        for (int j = 0; j < 8; j++) {
            uint32_t o = t16 + j * 4096;
            cp16(sb + SM_BH + o, bH + o);
            cp16(sb + SM_BL + o, bL + o);
        }
        cp_commit_wait();
    }
    __syncthreads();

    // ---- per-warp tile: rows rowbase..+31, cols nbase..+31 ----
    int rowbase = (wid & 1) * 32;
    int nbase = (wid >> 1) * 32;

    int mat = lane >> 3;
    int l7 = lane & 7;
    int axor[2]; uint32_t abyte[2];
    #pragma unroll
    for (int mi = 0; mi < 2; mi++) {
        int arow = rowbase + mi * 16 + (mat & 1) * 8 + l7;   // smem tile row 0..63
        axor[mi] = arow & 7;
        abyte[mi] = (uint32_t)(arow * 256);
    }
    int aco = mat >> 1;
    int bxor[2]; uint32_t bbyte[2];
    #pragma unroll
    for (int n16 = 0; n16 < 2; n16++) {
        int brow = nbase + n16 * 16 + (mat >> 1) * 8 + l7;   // B smem row 0..127
        bxor[n16] = brow & 7;
        bbyte[n16] = (uint32_t)(brow * 256);
    }
    int bco = mat & 1;

    float c[2][4][4];
    #pragma unroll
    for (int mi = 0; mi < 2; mi++)
        #pragma unroll
        for (int nj = 0; nj < 4; nj++)
            #pragma unroll
            for (int q = 0; q < 4; q++) c[mi][nj][q] = 0.0f;

    #pragma unroll
    for (int kc = 0; kc < 8; kc++) {
        int c0 = kc * 2;
        uint32_t ah[2][4], al[2][4], bh[2][4], bl[2][4];
        #pragma unroll
        for (int mi = 0; mi < 2; mi++) {
            uint32_t off = abyte[mi] + (((c0 + aco) ^ axor[mi]) << 4);
            ldsm4(ah[mi], sb + SM_AH + off);
            ldsm4(al[mi], sb + SM_AL + off);
        }
        #pragma unroll
        for (int n16 = 0; n16 < 2; n16++) {
            uint32_t off = bbyte[n16] + (((c0 + bco) ^ bxor[n16]) << 4);
            ldsm4(bh[n16], sb + SM_BH + off);
            ldsm4(bl[n16], sb + SM_BL + off);
        }
        #pragma unroll
        for (int mi = 0; mi < 2; mi++) {
            #pragma unroll
            for (int nj = 0; nj < 4; nj++) {
                const uint32_t* bhp = &bh[nj >> 1][(nj & 1) * 2];
                const uint32_t* blp = &bl[nj >> 1][(nj & 1) * 2];
                mma_bf16(c[mi][nj], ah[mi], bhp);
                mma_bf16(c[mi][nj], ah[mi], blp);
                mma_bf16(c[mi][nj], al[mi], bhp);
            }
        }
    }

    // ---- epilogue ----
    int gid = lane >> 2, tig = lane & 3;
    #pragma unroll
    for (int mi = 0; mi < 2; mi++) {
        int r_lo = row0 + rowbase + mi * 16 + gid;
        int r_hi = r_lo + 8;
        #pragma unroll
        for (int nj = 0; nj < 4; nj++) {
            int col = nbase + nj * 8 + tig * 2;   // even column
            if (MODE == 0) {
                if (r_lo < nrows)
                    *reinterpret_cast<float2*>(C + (size_t)r_lo * 128 + col) =
                        make_float2(c[mi][nj][0], c[mi][nj][1]);
                if (r_hi < nrows)
                    *reinterpret_cast<float2*>(C + (size_t)r_hi * 128 + col) =
                        make_float2(c[mi][nj][2], c[mi][nj][3]);
            } else {
                int chunk = col >> 3;
                uint32_t inrow = (uint32_t)((col & 7) * 2);
                if (r_lo < nrows) {
                    float v0 = c[mi][nj][0], v1 = c[mi][nj][1];
                    float h0 = __bfloat162float(__float2bfloat16(v0));
                    float h1 = __bfloat162float(__float2bfloat16(v1));
                    uint32_t off = (uint32_t)r_lo * 256u + (((chunk ^ (r_lo & 7)) << 4) + inrow);
                    *reinterpret_cast<uint32_t*>((char*)g_ah + off) = pack_bf(h0, h1);
                    *reinterpret_cast<uint32_t*>((char*)g_al + off) = pack_bf(v0 - h0, v1 - h1);
                }
                if (r_hi < nrows) {
                    float v0 = c[mi][nj][2], v1 = c[mi][nj][3];
                    float h0 = __bfloat162float(__float2bfloat16(v0));
                    float h1 = __bfloat162float(__float2bfloat16(v1));
                    uint32_t off = (uint32_t)r_hi * 256u + (((chunk ^ (r_hi & 7)) << 4) + inrow);
                    *reinterpret_cast<uint32_t*>((char*)g_ah + off) = pack_bf(h0, h1);
                    *reinterpret_cast<uint32_t*>((char*)g_al + off) = pack_bf(v0 - h0, v1 - h1);
                }
            }
        }
    }
}

// ---------------- preprocessing kernels ----------------
// fused: zero cnt + graph-start table (independent tasks, same grid)
__global__ void k_init(const int* __restrict__ batch) {
    int i = blockIdx.x * blockDim.x + threadIdx.x;
    if (i >= NN) return;
    g_cnt[i] = 0;
    int b = batch[i];
    int pb = (i == 0) ? -1 : batch[i - 1];
    for (int g = pb + 1; g <= b; g++) g_gstart[g] = i;
    if (i == NN - 1)
        for (int g = b + 1; g <= NG; g++) g_gstart[g] = NN;
}

__global__ void k_hist(const int* __restrict__ ei) {
    int e = blockIdx.x * blockDim.x + threadIdx.x;
    if (e < EE) {
        int c = ei[EE + e];  // col = destination
        atomicAdd(&g_cnt[c], 1);
    }
}

// single-block exclusive scan of g_cnt -> g_off, g_cur (1024 threads)
__global__ void k_scan() {
    __shared__ int warpsum[32];
    int tid = threadIdx.x;
    const int CH = (NN + 1023) / 1024;  // 98
    int start = tid * CH;
    int end = min(start + CH, NN);
    int s = 0;
    for (int i = start; i < end; i++) s += g_cnt[i];
    int lane = tid & 31, wid = tid >> 5;
    int incl = s;
    #pragma unroll
    for (int o = 1; o < 32; o <<= 1) {
        int v = __shfl_up_sync(0xFFFFFFFFu, incl, o);
        if (lane >= o) incl += v;
    }
    if (lane == 31) warpsum[wid] = incl;
    __syncthreads();
    if (wid == 0) {
        int v = warpsum[lane];
        #pragma unroll
        for (int o = 1; o < 32; o <<= 1) {
            int u = __shfl_up_sync(0xFFFFFFFFu, v, o);
            if (lane >= o) v += u;
        }
        warpsum[lane] = v;
    }
    __syncthreads();
    int base = (incl - s) + (wid > 0 ? warpsum[wid - 1] : 0);
    int run = base;
    for (int i = start; i < end; i++) {
        int cv = g_cnt[i];
        g_off[i] = run;
        g_cur[i] = run;
        run += cv;
    }
    if (tid == 1023) g_off[NN] = base;  // tail chunk always empty
}

__global__ void k_sort(const int* __restrict__ ei, const float* __restrict__ ew) {
    int e = blockIdx.x * blockDim.x + threadIdx.x;
    if (e < EE) {
        int d = ei[EE + e];
        int p = atomicAdd(&g_cur[d], 1);
        g_srcv[p] = ei[e];
        g_wv[p] = ew[e];
    }
}

__global__ void k_dinv() {
    int i = blockIdx.x * blockDim.x + threadIdx.x;
    if (i >= NN) return;
    float s = 1.0f;  // self-loop weight
    int p1 = g_off[i + 1];
    for (int p = g_off[i]; p < p1; p++) s += g_wv[p];
    g_dinv[i] = rsqrtf(s);
}

__global__ void k_coef() {
    int i = blockIdx.x * blockDim.x + threadIdx.x;
    if (i >= NN) return;
    float di = g_dinv[i];
    int p1 = g_off[i + 1];
    for (int p = g_off[i]; p < p1; p++)
        g_wv[p] = g_dinv[g_srcv[p]] * g_wv[p] * di;
}

// ---------------- aggregation: warp per node, CSR gather + bias + relu + BN partials --
__global__ void __launch_bounds__(256)
k_agg(const float* __restrict__ bias) {
    int lane = threadIdx.x & 31;
    int gw = (blockIdx.x * blockDim.x + threadIdx.x) >> 5;
    const float4* hl4 = (const float4*)g_hl;
    float4 bb = *((const float4*)bias + lane);
    float4 ps = make_float4(0, 0, 0, 0);
    float4 pq = make_float4(0, 0, 0, 0);

    for (int i = gw; i < NN; i += NWARPS) {
        float di = g_dinv[i];
        float sn = di * di;
        float4 v = hl4[i * 32 + lane];
        float4 acc;
        acc.x = sn * v.x; acc.y = sn * v.y; acc.z = sn * v.z; acc.w = sn * v.w;
        int p = g_off[i], p1 = g_off[i + 1];
        int s = 0; float w = 0.0f;
        if (p < p1) { s = g_srcv[p]; w = g_wv[p]; }
        while (p < p1) {
            int pn = p + 1;
            int sn2 = 0; float wn = 0.0f;
            if (pn < p1) { sn2 = g_srcv[pn]; wn = g_wv[pn]; }
            float4 u = hl4[s * 32 + lane];
            acc.x += w * u.x; acc.y += w * u.y; acc.z += w * u.z; acc.w += w * u.w;
            s = sn2; w = wn; p = pn;
        }
        acc.x = fmaxf(acc.x + bb.x, 0.0f);
        acc.y = fmaxf(acc.y + bb.y, 0.0f);
        acc.z = fmaxf(acc.z + bb.z, 0.0f);
        acc.w = fmaxf(acc.w + bb.w, 0.0f);
        ((float4*)g_t)[i * 32 + lane] = acc;
        ps.x += acc.x; ps.y += acc.y; ps.z += acc.z; ps.w += acc.w;
        pq.x += acc.x * acc.x; pq.y += acc.y * acc.y;
        pq.z += acc.z * acc.z; pq.w += acc.w * acc.w;
    }
    int c = lane * 4;
    float* o1 = g_psum + gw * DIM + c;
    o1[0] = ps.x; o1[1] = ps.y; o1[2] = ps.z; o1[3] = ps.w;
    float* o2 = g_psq + gw * DIM + c;
    o2[0] = pq.x; o2[1] = pq.y; o2[2] = pq.z; o2[3] = pq.w;
}

// ---------------- BN stage 2: per channel, deterministic tree reduction ----------------
__global__ void k_bnstat(const float* __restrict__ gamma, const float* __restrict__ beta) {
    __shared__ float ss[256];
    __shared__ float qq[256];
    int c = blockIdx.x;
    int tid = threadIdx.x;
    float s = 0.0f, q = 0.0f;
    for (int w = tid; w < NWARPS; w += 256) {
        s += g_psum[w * DIM + c];
        q += g_psq[w * DIM + c];
    }
    ss[tid] = s; qq[tid] = q;
    __syncthreads();
    for (int o = 128; o > 0; o >>= 1) {
        if (tid < o) { ss[tid] += ss[tid + o]; qq[tid] += qq[tid + o]; }
        __syncthreads();
    }
    if (tid == 0) {
        float mean = ss[0] / (float)NN;
        float var = qq[0] / (float)NN - mean * mean;
        float istd = rsqrtf(var + BN_EPS);
        float sc = gamma[c] * istd;
        g_scale[c] = sc;
        g_shift[c] = beta[c] - mean * sc;
    }
}

// ---------------- normalize: write xs output (+ split bf16 for next GEMM unless last) --
__global__ void k_norm(float* __restrict__ outxs, int l) {
    int idx = blockIdx.x * blockDim.x + threadIdx.x;  // float4 index
    if (idx >= NN * 32) return;
    int node = idx >> 5, c4 = idx & 31;
    float4 t = ((const float4*)g_t)[idx];
    float4 sc = ((const float4*)g_scale)[c4];
    float4 sh = ((const float4*)g_shift)[c4];
    float4 v;
    v.x = t.x * sc.x + sh.x; v.y = t.y * sc.y + sh.y;
    v.z = t.z * sc.z + sh.z; v.w = t.w * sc.w + sh.w;
    ((float4*)outxs)[(size_t)node * 96 + l * 32 + c4] = v;
    if (l < NLAYER - 1) {
        uint2 hp, lp; split4(v, hp, lp);
        uint32_t off = sw_addr(node, c4);
        *reinterpret_cast<uint2*>((char*)g_ah + off) = hp;
        *reinterpret_cast<uint2*>((char*)g_al + off) = lp;
    }
}

// ---------------- pooling: block per graph ----------------
__global__ void k_pool(const float* __restrict__ xs, float* __restrict__ outpool) {
    int g = blockIdx.x;
    int c = threadIdx.x;  // 384
    int a = g_gstart[g], b = g_gstart[g + 1];
    float s = 0.0f;
    for (int i = a; i < b; i++) s += xs[(size_t)i * 384 + c];
    outpool[(size_t)g * 384 + c] = s;
}

// ---------------- launch ----------------
extern "C" void kernel_launch(void* const* d_in, const int* in_sizes, int n_in,
                              void* d_out, int out_size) {
    const float* x = (const float*)d_in[0];
    const int* ei = (const int*)d_in[1];        // int32 (JAX x64 disabled)
    const float* ew = (const float*)d_in[2];
    const int* batch = (const int*)d_in[3];     // int32
    const float* fc_w = (const float*)d_in[4];
    const float* W = (const float*)d_in[5];
    const float* b = (const float*)d_in[6];
    const float* gamma = (const float*)d_in[7];
    const float* beta = (const float*)d_in[8];

    float* out = (float*)d_out;
    float* outpool = out;                    // [512, 384]
    float* outxs = out + (size_t)NG * 384;   // [N, 384]

    cudaFuncSetAttribute(k_gemm_mma<0>, cudaFuncAttributeMaxDynamicSharedMemorySize, SMEM_MMA);
    cudaFuncSetAttribute(k_gemm_mma<1>, cudaFuncAttributeMaxDynamicSharedMemorySize, SMEM_MMA);

    float* g_hl_p; cudaGetSymbolAddress((void**)&g_hl_p, g_hl);
    __nv_bfloat16* g_wh_p; cudaGetSymbolAddress((void**)&g_wh_p, g_wh);
    __nv_bfloat16* g_wl_p; cudaGetSymbolAddress((void**)&g_wl_p, g_wl);

    // convert x + all weights, then the two graph-independent GEMMs first
    k_cvtall<<<(CVT_XP + 4 * 128 * 32 + 255) / 256, 256>>>(x, fc_w, W);
    // h0 = x @ fc_w^T  (writes split bf16 in place)
    k_gemm_mma<1><<<NT64, 256, SMEM_MMA>>>(g_wh_p, g_wl_p, nullptr, NN);
    // layer 0 linear: hl = h0 @ W0^T (fp32 out)
    k_gemm_mma<0><<<NT64, 256, SMEM_MMA>>>(g_wh_p + 16384, g_wl_p + 16384, g_hl_p, NN);

    // CSR preprocessing
    k_init<<<(NN + 255) / 256, 256>>>(batch);
    k_hist<<<(EE + 255) / 256, 256>>>(ei);
    k_scan<<<1, 1024>>>();
    k_sort<<<(EE + 255) / 256, 256>>>(ei, ew);
    k_dinv<<<(NN + 255) / 256, 256>>>();
    k_coef<<<(NN + 255) / 256, 256>>>();

    for (int l = 0; l < NLAYER; l++) {
        if (l > 0)  // layer-l linear from previous norm output
            k_gemm_mma<0><<<NT64, 256, SMEM_MMA>>>(g_wh_p + (l + 1) * 16384,
                                                   g_wl_p + (l + 1) * 16384, g_hl_p, NN);
        k_agg<<<AGG_BLOCKS, 256>>>(b + l * DIM);
        k_bnstat<<<DIM, 256>>>(gamma + l * DIM, beta + l * DIM);
        k_norm<<<(NN * 32 + 255) / 256, 256>>>(outxs, l);
    }

    k_pool<<<NG, 384>>>(outxs, outpool);
}